// round 1
// baseline (speedup 1.0000x reference)
#include <cuda_runtime.h>
#include <cuda_bf16.h>

// SoftThresholdAttention: B=2, N=4096, C=256, H=4, Dh=64
// d_in: 0=x, 1=q_w, 2=q_b, 3=k_w, 4=k_b, 5=v_w, 6=v_b, 7=o_w, 8=o_b, 9=tau

#define PITCH 65

// Scratch (device globals; no allocation allowed)
__device__ float g_Q[8 * 4096 * 64];   // [b*H+h][n][d]
__device__ float g_K[8 * 4096 * 64];
__device__ float g_V[8 * 4096 * 64];
__device__ float g_A[8192 * 256];      // attention output, [t][c]

// ---------------------------------------------------------------------------
// QKV projection: out[t,c] = sum_d x[t,d] * W[c,d] + b[c]; store [bh][n][d]
// ---------------------------------------------------------------------------
__global__ __launch_bounds__(256) void qkv_kernel(
    const float* __restrict__ x,
    const float* __restrict__ qw, const float* __restrict__ qb,
    const float* __restrict__ kw, const float* __restrict__ kb,
    const float* __restrict__ vw, const float* __restrict__ vb)
{
    __shared__ float As[64 * PITCH];
    __shared__ float Ws[64 * PITCH];

    const int z = blockIdx.z;
    const float* __restrict__ W    = (z == 0) ? qw : (z == 1) ? kw : vw;
    const float* __restrict__ bias = (z == 0) ? qb : (z == 1) ? kb : vb;
    float* __restrict__ dst        = (z == 0) ? g_Q : (z == 1) ? g_K : g_V;

    const int tr = blockIdx.x * 64;
    const int tc = blockIdx.y * 64;
    const int tid = threadIdx.x;
    const int tx = tid & 15, ty = tid >> 4;

    float acc[4][4] = {};

    for (int kb_ = 0; kb_ < 256; kb_ += 64) {
        for (int idx = tid; idx < 64 * 64; idx += 256) {
            int r = idx >> 6, d = idx & 63;
            As[r * PITCH + d] = x[(tr + r) * 256 + kb_ + d];
            Ws[r * PITCH + d] = W[(tc + r) * 256 + kb_ + d];
        }
        __syncthreads();
        #pragma unroll 8
        for (int d = 0; d < 64; d++) {
            float a[4], b[4];
            #pragma unroll
            for (int i = 0; i < 4; i++) a[i] = As[(ty * 4 + i) * PITCH + d];
            #pragma unroll
            for (int j = 0; j < 4; j++) b[j] = Ws[(tx + 16 * j) * PITCH + d];
            #pragma unroll
            for (int i = 0; i < 4; i++)
                #pragma unroll
                for (int j = 0; j < 4; j++)
                    acc[i][j] += a[i] * b[j];
        }
        __syncthreads();
    }

    #pragma unroll
    for (int i = 0; i < 4; i++) {
        int t = tr + ty * 4 + i;
        int b_ = t >> 12, n = t & 4095;
        #pragma unroll
        for (int j = 0; j < 4; j++) {
            int c = tc + tx + 16 * j;
            int h = c >> 6, dd = c & 63;
            dst[((b_ * 4 + h) * 4096 + n) * 64 + dd] = acc[i][j] + bias[c];
        }
    }
}

// ---------------------------------------------------------------------------
// Flash attention with soft-threshold gate.
// grid: (64 q-tiles, 8 bh). block 256. dyn smem: 4 * 64*PITCH floats.
// ---------------------------------------------------------------------------
__global__ __launch_bounds__(256) void attn_kernel(const float* __restrict__ tau_p)
{
    extern __shared__ float sm[];
    float* Qs = sm;
    float* Ks = sm + 64 * PITCH;
    float* Vs = sm + 2 * 64 * PITCH;
    float* Ps = sm + 3 * 64 * PITCH;

    const int qt = blockIdx.x, bh = blockIdx.y;
    const int tid = threadIdx.x;
    const int tx = tid & 15, ty = tid >> 4;
    const float tau = tau_p[0];
    const float scale = 0.0625f;   // 256^-0.5

    const float* __restrict__ Qg = g_Q + (bh * 4096 + qt * 64) * 64;
    const float* __restrict__ Kg = g_K + bh * 4096 * 64;
    const float* __restrict__ Vg = g_V + bh * 4096 * 64;

    for (int idx = tid; idx < 4096; idx += 256) {
        int r = idx >> 6, d = idx & 63;
        Qs[r * PITCH + d] = Qg[idx];
    }

    float m[4], l[4], Oacc[4][4] = {};
    #pragma unroll
    for (int i = 0; i < 4; i++) { m[i] = 0.0f; l[i] = 0.0f; }

    for (int kt = 0; kt < 64; kt++) {
        __syncthreads();   // protect Ks/Vs/Ps from previous iteration readers
        for (int idx = tid; idx < 4096; idx += 256) {
            int r = idx >> 6, d = idx & 63;
            Ks[r * PITCH + d] = Kg[kt * 4096 + idx];
            Vs[r * PITCH + d] = Vg[kt * 4096 + idx];
        }
        __syncthreads();

        // S = Q K^T
        float s[4][4] = {};
        #pragma unroll 8
        for (int d = 0; d < 64; d++) {
            float a[4], b[4];
            #pragma unroll
            for (int i = 0; i < 4; i++) a[i] = Qs[(ty * 4 + i) * PITCH + d];
            #pragma unroll
            for (int j = 0; j < 4; j++) b[j] = Ks[(tx + 16 * j) * PITCH + d];
            #pragma unroll
            for (int i = 0; i < 4; i++)
                #pragma unroll
                for (int j = 0; j < 4; j++)
                    s[i][j] += a[i] * b[j];
        }

        // scale + gate: keep only v > tau (relu(where(|v|>tau,v,0)) == this)
        #pragma unroll
        for (int i = 0; i < 4; i++)
            #pragma unroll
            for (int j = 0; j < 4; j++) {
                float v = s[i][j] * scale;
                s[i][j] = (v > tau) ? v : 0.0f;
            }

        // online softmax per row (rows split across 16-lane half-groups)
        #pragma unroll
        for (int i = 0; i < 4; i++) {
            float tm = fmaxf(fmaxf(s[i][0], s[i][1]), fmaxf(s[i][2], s[i][3]));
            #pragma unroll
            for (int mask = 8; mask >= 1; mask >>= 1)
                tm = fmaxf(tm, __shfl_xor_sync(0xffffffffu, tm, mask));
            float mn = fmaxf(m[i], tm);
            float corr = __expf(m[i] - mn);
            float ps = 0.0f;
            #pragma unroll
            for (int j = 0; j < 4; j++) {
                float p = __expf(s[i][j] - mn);
                s[i][j] = p;
                ps += p;
            }
            #pragma unroll
            for (int mask = 8; mask >= 1; mask >>= 1)
                ps += __shfl_xor_sync(0xffffffffu, ps, mask);
            l[i] = l[i] * corr + ps;
            m[i] = mn;
            #pragma unroll
            for (int j = 0; j < 4; j++) Oacc[i][j] *= corr;
        }

        // store P
        #pragma unroll
        for (int i = 0; i < 4; i++)
            #pragma unroll
            for (int j = 0; j < 4; j++)
                Ps[(ty * 4 + i) * PITCH + tx + 16 * j] = s[i][j];
        __syncthreads();

        // O += P V
        #pragma unroll 8
        for (int k = 0; k < 64; k++) {
            float p[4], v[4];
            #pragma unroll
            for (int i = 0; i < 4; i++) p[i] = Ps[(ty * 4 + i) * PITCH + k];
            #pragma unroll
            for (int j = 0; j < 4; j++) v[j] = Vs[k * PITCH + tx + 16 * j];
            #pragma unroll
            for (int i = 0; i < 4; i++)
                #pragma unroll
                for (int j = 0; j < 4; j++)
                    Oacc[i][j] += p[i] * v[j];
        }
    }

    // write normalized output to g_A in [t][c] layout
    const int b_ = bh >> 2, h = bh & 3;
    #pragma unroll
    for (int i = 0; i < 4; i++) {
        int n = qt * 64 + ty * 4 + i;
        float inv_l = 1.0f / l[i];
        #pragma unroll
        for (int j = 0; j < 4; j++) {
            int c = h * 64 + tx + 16 * j;
            g_A[(b_ * 4096 + n) * 256 + c] = Oacc[i][j] * inv_l;
        }
    }
}

// ---------------------------------------------------------------------------
// Output projection: out[t,c] = sum_d g_A[t,d] * o_w[c,d] + o_b[c]
// ---------------------------------------------------------------------------
__global__ __launch_bounds__(256) void oproj_kernel(
    const float* __restrict__ ow, const float* __restrict__ ob,
    float* __restrict__ out)
{
    __shared__ float As[64 * PITCH];
    __shared__ float Ws[64 * PITCH];

    const int tr = blockIdx.x * 64;
    const int tc = blockIdx.y * 64;
    const int tid = threadIdx.x;
    const int tx = tid & 15, ty = tid >> 4;

    float acc[4][4] = {};

    for (int kb_ = 0; kb_ < 256; kb_ += 64) {
        for (int idx = tid; idx < 64 * 64; idx += 256) {
            int r = idx >> 6, d = idx & 63;
            As[r * PITCH + d] = g_A[(tr + r) * 256 + kb_ + d];
            Ws[r * PITCH + d] = ow[(tc + r) * 256 + kb_ + d];
        }
        __syncthreads();
        #pragma unroll 8
        for (int d = 0; d < 64; d++) {
            float a[4], b[4];
            #pragma unroll
            for (int i = 0; i < 4; i++) a[i] = As[(ty * 4 + i) * PITCH + d];
            #pragma unroll
            for (int j = 0; j < 4; j++) b[j] = Ws[(tx + 16 * j) * PITCH + d];
            #pragma unroll
            for (int i = 0; i < 4; i++)
                #pragma unroll
                for (int j = 0; j < 4; j++)
                    acc[i][j] += a[i] * b[j];
        }
        __syncthreads();
    }

    #pragma unroll
    for (int i = 0; i < 4; i++) {
        int t = tr + ty * 4 + i;
        #pragma unroll
        for (int j = 0; j < 4; j++) {
            int c = tc + tx + 16 * j;
            out[t * 256 + c] = acc[i][j] + ob[c];
        }
    }
}

// ---------------------------------------------------------------------------
extern "C" void kernel_launch(void* const* d_in, const int* in_sizes, int n_in,
                              void* d_out, int out_size)
{
    const float* x   = (const float*)d_in[0];
    const float* qw  = (const float*)d_in[1];
    const float* qb  = (const float*)d_in[2];
    const float* kw  = (const float*)d_in[3];
    const float* kb  = (const float*)d_in[4];
    const float* vw  = (const float*)d_in[5];
    const float* vb  = (const float*)d_in[6];
    const float* ow  = (const float*)d_in[7];
    const float* ob  = (const float*)d_in[8];
    const float* tau = (const float*)d_in[9];
    float* out = (float*)d_out;

    // QKV projections
    dim3 gq(128, 4, 3);
    qkv_kernel<<<gq, 256>>>(x, qw, qb, kw, kb, vw, vb);

    // flash attention (dynamic smem: 4 tiles of 64*PITCH floats)
    static bool attr_set = false;
    const int smem_bytes = 4 * 64 * PITCH * sizeof(float);
    if (!attr_set) {
        cudaFuncSetAttribute(attn_kernel,
                             cudaFuncAttributeMaxDynamicSharedMemorySize,
                             smem_bytes);
        attr_set = true;
    }
    dim3 ga(64, 8);
    attn_kernel<<<ga, 256, smem_bytes>>>(tau);

    // output projection
    dim3 go(128, 4);
    oproj_kernel<<<go, 256>>>(ow, ob, out);
}

// round 2
// speedup vs baseline: 1.5566x; 1.5566x over previous
#include <cuda_runtime.h>
#include <cuda_bf16.h>

// SoftThresholdAttention: B=2, N=4096, C=256, H=4, Dh=64
// d_in: 0=x, 1=q_w, 2=q_b, 3=k_w, 4=k_b, 5=v_w, 6=v_b, 7=o_w, 8=o_b, 9=tau

#define PITCH 65

// Scratch (device globals; no allocation allowed)
__device__ float g_Q[8 * 4096 * 64];   // [b*H+h][n][d]
__device__ float g_K[8 * 4096 * 64];
__device__ float g_V[8 * 4096 * 64];
__device__ float g_A[8192 * 256];      // attention output, [t][c]

// ---------------------------------------------------------------------------
// QKV projection: out[t,c] = sum_d x[t,d] * W[c,d] + b[c]; store [bh][n][d]
// ---------------------------------------------------------------------------
__global__ __launch_bounds__(256) void qkv_kernel(
    const float* __restrict__ x,
    const float* __restrict__ qw, const float* __restrict__ qb,
    const float* __restrict__ kw, const float* __restrict__ kb,
    const float* __restrict__ vw, const float* __restrict__ vb)
{
    __shared__ float As[64 * PITCH];
    __shared__ float Ws[64 * PITCH];

    const int z = blockIdx.z;
    const float* __restrict__ W    = (z == 0) ? qw : (z == 1) ? kw : vw;
    const float* __restrict__ bias = (z == 0) ? qb : (z == 1) ? kb : vb;
    float* __restrict__ dst        = (z == 0) ? g_Q : (z == 1) ? g_K : g_V;

    const int tr = blockIdx.x * 64;
    const int tc = blockIdx.y * 64;
    const int tid = threadIdx.x;
    const int tx = tid & 15, ty = tid >> 4;

    float acc[4][4] = {};

    for (int kb_ = 0; kb_ < 256; kb_ += 64) {
        for (int idx = tid; idx < 64 * 64; idx += 256) {
            int r = idx >> 6, d = idx & 63;
            As[r * PITCH + d] = x[(tr + r) * 256 + kb_ + d];
            Ws[r * PITCH + d] = W[(tc + r) * 256 + kb_ + d];
        }
        __syncthreads();
        #pragma unroll 8
        for (int d = 0; d < 64; d++) {
            float a[4], b[4];
            #pragma unroll
            for (int i = 0; i < 4; i++) a[i] = As[(ty * 4 + i) * PITCH + d];
            #pragma unroll
            for (int j = 0; j < 4; j++) b[j] = Ws[(tx + 16 * j) * PITCH + d];
            #pragma unroll
            for (int i = 0; i < 4; i++)
                #pragma unroll
                for (int j = 0; j < 4; j++)
                    acc[i][j] += a[i] * b[j];
        }
        __syncthreads();
    }

    #pragma unroll
    for (int i = 0; i < 4; i++) {
        int t = tr + ty * 4 + i;
        int b_ = t >> 12, n = t & 4095;
        #pragma unroll
        for (int j = 0; j < 4; j++) {
            int c = tc + tx + 16 * j;
            int h = c >> 6, dd = c & 63;
            dst[((b_ * 4 + h) * 4096 + n) * 64 + dd] = acc[i][j] + bias[c];
        }
    }
}

// ---------------------------------------------------------------------------
// Sparse-gated attention (no online softmax needed: all gated scores >= 0 and
// bounded, so denom = 4096 + sum(e^s - 1 over s>tau), O = sumV + sum w*V).
// grid: (64 q-tiles, 8 bh). block 256 (8 warps x 8 rows). k-tile = 128.
// ---------------------------------------------------------------------------
__global__ __launch_bounds__(256, 2) void attn_kernel(const float* __restrict__ tau_p)
{
    extern __shared__ float sm[];
    float* Qs    = sm;                        // 64 x PITCH
    float* Ks    = sm + 64 * PITCH;           // 128 x PITCH
    float* Vs    = sm + (64 + 128) * PITCH;   // 128 x PITCH
    float* sumVp = sm + (64 + 256) * PITCH;   // 4 x 68

    const int qt = blockIdx.x, bh = blockIdx.y;
    const int tid  = threadIdx.x;
    const int warp = tid >> 5;
    const int lane = tid & 31;
    const int r0   = warp * 8;
    const float tau   = tau_p[0];
    const float scale = 0.0625f;   // 256^-0.5

    const float* __restrict__ Qg = g_Q + (bh * 4096 + qt * 64) * 64;
    const float* __restrict__ Kg = g_K + bh * 4096 * 64;
    const float* __restrict__ Vg = g_V + bh * 4096 * 64;

    // load Q tile (64 x 64)
    for (int idx = tid; idx < 4096; idx += 256) {
        int r = idx >> 6, d = idx & 63;
        Qs[r * PITCH + d] = Qg[idx];
    }

    // per-lane state
    float O[8][2] = {};     // O[row i][d = lane, lane+32]
    float dl[8]   = {};     // per-lane denominator partials per row
    float sv      = 0.0f;   // sumV partial: this thread's (g, d) slice
    const int svg = tid >> 6;       // 0..3 -> k-range [g*32, g*32+32)
    const int svd = tid & 63;

    for (int kt = 0; kt < 32; kt++) {
        __syncthreads();   // previous tile's readers done
        // load K,V tiles (128 x 64) with float4
        {
            const float4* K4 = (const float4*)(Kg + kt * 128 * 64);
            const float4* V4 = (const float4*)(Vg + kt * 128 * 64);
            #pragma unroll
            for (int it = 0; it < 8; it++) {
                int idx = tid + it * 256;          // < 2048
                int r = idx >> 4, d = (idx & 15) * 4;
                float4 kv = K4[idx];
                float* p = &Ks[r * PITCH + d];
                p[0] = kv.x; p[1] = kv.y; p[2] = kv.z; p[3] = kv.w;
                float4 vv = V4[idx];
                float* q = &Vs[r * PITCH + d];
                q[0] = vv.x; q[1] = vv.y; q[2] = vv.z; q[3] = vv.w;
            }
        }
        __syncthreads();

        // sumV partial: thread sums V[k][svd] over its 32-key range
        #pragma unroll 8
        for (int k = 0; k < 32; k++)
            sv += Vs[(svg * 32 + k) * PITCH + svd];

        // S = Q K^T : s[8 rows][4 cols = lane + 32*jc]
        float s[8][4] = {};
        #pragma unroll 8
        for (int d = 0; d < 64; d++) {
            float a[8], b[4];
            #pragma unroll
            for (int i = 0; i < 8; i++) a[i] = Qs[(r0 + i) * PITCH + d];
            #pragma unroll
            for (int jc = 0; jc < 4; jc++) b[jc] = Ks[(lane + 32 * jc) * PITCH + d];
            #pragma unroll
            for (int i = 0; i < 8; i++)
                #pragma unroll
                for (int jc = 0; jc < 4; jc++)
                    s[i][jc] += a[i] * b[jc];
        }

        // gate: w = e^v - 1 if v > tau else 0 ; accumulate denom partials
        #pragma unroll
        for (int i = 0; i < 8; i++) {
            #pragma unroll
            for (int jc = 0; jc < 4; jc++) {
                float v = s[i][jc] * scale;
                float w = (v > tau) ? (__expf(v) - 1.0f) : 0.0f;
                s[i][jc] = w;
                dl[i] += w;
            }
        }

        // sparse PV scatter: ballot nonzeros, broadcast, all lanes update O
        #pragma unroll
        for (int i = 0; i < 8; i++) {
            #pragma unroll
            for (int jc = 0; jc < 4; jc++) {
                unsigned mask = __ballot_sync(0xffffffffu, s[i][jc] > 0.0f);
                while (mask) {
                    int src = __ffs(mask) - 1;
                    mask &= mask - 1;
                    float wb = __shfl_sync(0xffffffffu, s[i][jc], src);
                    int col = src + 32 * jc;
                    O[i][0] += wb * Vs[col * PITCH + lane];
                    O[i][1] += wb * Vs[col * PITCH + lane + 32];
                }
            }
        }
    }

    // combine sumV partials
    __syncthreads();
    sumVp[svg * 68 + svd] = sv;
    __syncthreads();
    float sv0 = sumVp[lane]      + sumVp[68 + lane]      + sumVp[136 + lane]      + sumVp[204 + lane];
    float sv1 = sumVp[lane + 32] + sumVp[68 + lane + 32] + sumVp[136 + lane + 32] + sumVp[204 + lane + 32];

    // finalize: denom per row via warp reduction, write to g_A [t][c]
    const int b_ = bh >> 2, h = bh & 3;
    const int tbase = (b_ * 4096 + qt * 64);
    #pragma unroll
    for (int i = 0; i < 8; i++) {
        float ds = dl[i];
        #pragma unroll
        for (int msk = 16; msk >= 1; msk >>= 1)
            ds += __shfl_xor_sync(0xffffffffu, ds, msk);
        float inv = 1.0f / (4096.0f + ds);
        int t = tbase + r0 + i;
        g_A[t * 256 + h * 64 + lane]      = (sv0 + O[i][0]) * inv;
        g_A[t * 256 + h * 64 + lane + 32] = (sv1 + O[i][1]) * inv;
    }
}

// ---------------------------------------------------------------------------
// Output projection: out[t,c] = sum_d g_A[t,d] * o_w[c,d] + o_b[c]
// ---------------------------------------------------------------------------
__global__ __launch_bounds__(256) void oproj_kernel(
    const float* __restrict__ ow, const float* __restrict__ ob,
    float* __restrict__ out)
{
    __shared__ float As[64 * PITCH];
    __shared__ float Ws[64 * PITCH];

    const int tr = blockIdx.x * 64;
    const int tc = blockIdx.y * 64;
    const int tid = threadIdx.x;
    const int tx = tid & 15, ty = tid >> 4;

    float acc[4][4] = {};

    for (int kb_ = 0; kb_ < 256; kb_ += 64) {
        for (int idx = tid; idx < 64 * 64; idx += 256) {
            int r = idx >> 6, d = idx & 63;
            As[r * PITCH + d] = g_A[(tr + r) * 256 + kb_ + d];
            Ws[r * PITCH + d] = ow[(tc + r) * 256 + kb_ + d];
        }
        __syncthreads();
        #pragma unroll 8
        for (int d = 0; d < 64; d++) {
            float a[4], b[4];
            #pragma unroll
            for (int i = 0; i < 4; i++) a[i] = As[(ty * 4 + i) * PITCH + d];
            #pragma unroll
            for (int j = 0; j < 4; j++) b[j] = Ws[(tx + 16 * j) * PITCH + d];
            #pragma unroll
            for (int i = 0; i < 4; i++)
                #pragma unroll
                for (int j = 0; j < 4; j++)
                    acc[i][j] += a[i] * b[j];
        }
        __syncthreads();
    }

    #pragma unroll
    for (int i = 0; i < 4; i++) {
        int t = tr + ty * 4 + i;
        #pragma unroll
        for (int j = 0; j < 4; j++) {
            int c = tc + tx + 16 * j;
            out[t * 256 + c] = acc[i][j] + ob[c];
        }
    }
}

// ---------------------------------------------------------------------------
extern "C" void kernel_launch(void* const* d_in, const int* in_sizes, int n_in,
                              void* d_out, int out_size)
{
    const float* x   = (const float*)d_in[0];
    const float* qw  = (const float*)d_in[1];
    const float* qb  = (const float*)d_in[2];
    const float* kw  = (const float*)d_in[3];
    const float* kb  = (const float*)d_in[4];
    const float* vw  = (const float*)d_in[5];
    const float* vb  = (const float*)d_in[6];
    const float* ow  = (const float*)d_in[7];
    const float* ob  = (const float*)d_in[8];
    const float* tau = (const float*)d_in[9];
    float* out = (float*)d_out;

    // QKV projections
    dim3 gq(128, 4, 3);
    qkv_kernel<<<gq, 256>>>(x, qw, qb, kw, kb, vw, vb);

    // sparse-gated attention
    static bool attr_set = false;
    const int smem_bytes = ((64 + 256) * PITCH + 4 * 68) * (int)sizeof(float);
    if (!attr_set) {
        cudaFuncSetAttribute(attn_kernel,
                             cudaFuncAttributeMaxDynamicSharedMemorySize,
                             smem_bytes);
        attr_set = true;
    }
    dim3 ga(64, 8);
    attn_kernel<<<ga, 256, smem_bytes>>>(tau);

    // output projection
    dim3 go(128, 4);
    oproj_kernel<<<go, 256>>>(ow, ob, out);
}

// round 3
// speedup vs baseline: 1.6778x; 1.0778x over previous
#include <cuda_runtime.h>
#include <cuda_bf16.h>

// SoftThresholdAttention: B=2, N=4096, C=256, H=4, Dh=64
// d_in: 0=x, 1=q_w, 2=q_b, 3=k_w, 4=k_b, 5=v_w, 6=v_b, 7=o_w, 8=o_b, 9=tau

#define PITCH 65
#define QP 66   // transposed-Q pitch (even: 8B-aligned row pairs)

// Scratch (device globals; no allocation allowed)
__device__ float g_Q[8 * 4096 * 64];   // [b*H+h][n][d]
__device__ float g_K[8 * 4096 * 64];
__device__ float g_V[8 * 4096 * 64];
__device__ float g_A[8192 * 256];      // attention output, [t][c]

// ---- packed fp32x2 helpers (Blackwell FFMA2) -------------------------------
__device__ __forceinline__ unsigned long long pack2(float lo, float hi) {
    unsigned long long r;
    asm("mov.b64 %0, {%1, %2};" : "=l"(r) : "f"(lo), "f"(hi));
    return r;
}
__device__ __forceinline__ void fma2acc(unsigned long long& d,
                                        unsigned long long a,
                                        unsigned long long b) {
    asm("fma.rn.f32x2 %0, %1, %2, %0;" : "+l"(d) : "l"(a), "l"(b));
}
__device__ __forceinline__ float2 unpack2(unsigned long long v) {
    float lo, hi;
    asm("mov.b64 {%0, %1}, %2;" : "=f"(lo), "=f"(hi) : "l"(v));
    return make_float2(lo, hi);
}

// ---------------------------------------------------------------------------
// QKV projection: out[t,c] = sum_d x[t,d] * W[c,d] + b[c]; store [bh][n][d]
// ---------------------------------------------------------------------------
__global__ __launch_bounds__(256) void qkv_kernel(
    const float* __restrict__ x,
    const float* __restrict__ qw, const float* __restrict__ qb,
    const float* __restrict__ kw, const float* __restrict__ kb,
    const float* __restrict__ vw, const float* __restrict__ vb)
{
    __shared__ float As[64 * PITCH];
    __shared__ float Ws[64 * PITCH];

    const int z = blockIdx.z;
    const float* __restrict__ W    = (z == 0) ? qw : (z == 1) ? kw : vw;
    const float* __restrict__ bias = (z == 0) ? qb : (z == 1) ? kb : vb;
    float* __restrict__ dst        = (z == 0) ? g_Q : (z == 1) ? g_K : g_V;

    const int tr = blockIdx.x * 64;
    const int tc = blockIdx.y * 64;
    const int tid = threadIdx.x;
    const int tx = tid & 15, ty = tid >> 4;

    float acc[4][4] = {};

    for (int kb_ = 0; kb_ < 256; kb_ += 64) {
        for (int idx = tid; idx < 64 * 64; idx += 256) {
            int r = idx >> 6, d = idx & 63;
            As[r * PITCH + d] = x[(tr + r) * 256 + kb_ + d];
            Ws[r * PITCH + d] = W[(tc + r) * 256 + kb_ + d];
        }
        __syncthreads();
        #pragma unroll 8
        for (int d = 0; d < 64; d++) {
            float a[4], b[4];
            #pragma unroll
            for (int i = 0; i < 4; i++) a[i] = As[(ty * 4 + i) * PITCH + d];
            #pragma unroll
            for (int j = 0; j < 4; j++) b[j] = Ws[(tx + 16 * j) * PITCH + d];
            #pragma unroll
            for (int i = 0; i < 4; i++)
                #pragma unroll
                for (int j = 0; j < 4; j++)
                    acc[i][j] += a[i] * b[j];
        }
        __syncthreads();
    }

    #pragma unroll
    for (int i = 0; i < 4; i++) {
        int t = tr + ty * 4 + i;
        int b_ = t >> 12, n = t & 4095;
        #pragma unroll
        for (int j = 0; j < 4; j++) {
            int c = tc + tx + 16 * j;
            int h = c >> 6, dd = c & 63;
            dst[((b_ * 4 + h) * 4096 + n) * 64 + dd] = acc[i][j] + bias[c];
        }
    }
}

// ---------------------------------------------------------------------------
// Sparse-gated attention. QK^T uses packed fma.rn.f32x2 (FFMA2):
//   - Q tile stored transposed (QsT[d][r]) so row-pairs load as one LDS.64
//   - K value duplicated into both packed lanes
// denom = 4096 + sum(e^v - 1 over v>tau); O = (sumV + sum w*V) / denom.
// grid: (64 q-tiles, 8 bh). block 256 (8 warps x 8 rows). k-tile = 128.
// ---------------------------------------------------------------------------
__global__ __launch_bounds__(256, 2) void attn_kernel(const float* __restrict__ tau_p)
{
    extern __shared__ float sm[];
    float* QsT   = sm;                               // 64 x QP (transposed)
    float* Ks    = sm + 64 * QP;                     // 128 x PITCH
    float* Vs    = sm + 64 * QP + 128 * PITCH;       // 128 x PITCH
    float* sumVp = sm + 64 * QP + 256 * PITCH;       // 4 x 68

    const int qt = blockIdx.x, bh = blockIdx.y;
    const int tid  = threadIdx.x;
    const int warp = tid >> 5;
    const int lane = tid & 31;
    const int r0   = warp * 8;
    const float tau   = tau_p[0];
    const float scale = 0.0625f;   // 256^-0.5

    const float* __restrict__ Qg = g_Q + (bh * 4096 + qt * 64) * 64;
    const float* __restrict__ Kg = g_K + bh * 4096 * 64;
    const float* __restrict__ Vg = g_V + bh * 4096 * 64;

    // load Q tile (64 x 64) transposed: QsT[d][r] = Q[r][d]
    for (int idx = tid; idx < 4096; idx += 256) {
        int r = idx >> 6, d = idx & 63;
        QsT[d * QP + r] = Qg[idx];
    }

    // per-lane state
    float O[8][2] = {};     // O[row i][d = lane, lane+32]
    float dl[8]   = {};     // per-lane denominator partials per row
    float sv      = 0.0f;   // sumV partial: this thread's (g, d) slice
    const int svg = tid >> 6;       // 0..3 -> k-range [g*32, g*32+32)
    const int svd = tid & 63;

    for (int kt = 0; kt < 32; kt++) {
        __syncthreads();   // previous tile's readers done
        // load K,V tiles (128 x 64) with float4
        {
            const float4* K4 = (const float4*)(Kg + kt * 128 * 64);
            const float4* V4 = (const float4*)(Vg + kt * 128 * 64);
            #pragma unroll
            for (int it = 0; it < 8; it++) {
                int idx = tid + it * 256;          // < 2048
                int r = idx >> 4, d = (idx & 15) * 4;
                float4 kv = K4[idx];
                float* p = &Ks[r * PITCH + d];
                p[0] = kv.x; p[1] = kv.y; p[2] = kv.z; p[3] = kv.w;
                float4 vv = V4[idx];
                float* q = &Vs[r * PITCH + d];
                q[0] = vv.x; q[1] = vv.y; q[2] = vv.z; q[3] = vv.w;
            }
        }
        __syncthreads();

        // sumV partial: thread sums V[k][svd] over its 32-key range
        #pragma unroll 8
        for (int k = 0; k < 32; k++)
            sv += Vs[(svg * 32 + k) * PITCH + svd];

        // S = Q K^T via packed FFMA2.
        // s2[p][jc] = ( S[r0+2p][lane+32jc], S[r0+2p+1][lane+32jc] )
        unsigned long long s2[4][4];
        #pragma unroll
        for (int p = 0; p < 4; p++)
            #pragma unroll
            for (int jc = 0; jc < 4; jc++) s2[p][jc] = 0ull;

        #pragma unroll 16
        for (int d = 0; d < 64; d++) {
            const float* qrow = &QsT[d * QP + r0];
            unsigned long long ra[4];
            #pragma unroll
            for (int p = 0; p < 4; p++)
                ra[p] = *(const unsigned long long*)(qrow + 2 * p);
            unsigned long long bb[4];
            #pragma unroll
            for (int jc = 0; jc < 4; jc++) {
                float b = Ks[(lane + 32 * jc) * PITCH + d];
                bb[jc] = pack2(b, b);
            }
            #pragma unroll
            for (int p = 0; p < 4; p++)
                #pragma unroll
                for (int jc = 0; jc < 4; jc++)
                    fma2acc(s2[p][jc], ra[p], bb[jc]);
        }

        // unpack
        float s[8][4];
        #pragma unroll
        for (int p = 0; p < 4; p++)
            #pragma unroll
            for (int jc = 0; jc < 4; jc++) {
                float2 v = unpack2(s2[p][jc]);
                s[2 * p][jc]     = v.x;
                s[2 * p + 1][jc] = v.y;
            }

        // gate: w = e^v - 1 if v > tau else 0 ; accumulate denom partials
        #pragma unroll
        for (int i = 0; i < 8; i++) {
            #pragma unroll
            for (int jc = 0; jc < 4; jc++) {
                float v = s[i][jc] * scale;
                float w = (v > tau) ? (__expf(v) - 1.0f) : 0.0f;
                s[i][jc] = w;
                dl[i] += w;
            }
        }

        // sparse PV scatter: ballot nonzeros, broadcast, all lanes update O
        #pragma unroll
        for (int i = 0; i < 8; i++) {
            #pragma unroll
            for (int jc = 0; jc < 4; jc++) {
                unsigned mask = __ballot_sync(0xffffffffu, s[i][jc] > 0.0f);
                while (mask) {
                    int src = __ffs(mask) - 1;
                    mask &= mask - 1;
                    float wb = __shfl_sync(0xffffffffu, s[i][jc], src);
                    int col = src + 32 * jc;
                    O[i][0] += wb * Vs[col * PITCH + lane];
                    O[i][1] += wb * Vs[col * PITCH + lane + 32];
                }
            }
        }
    }

    // combine sumV partials
    __syncthreads();
    sumVp[svg * 68 + svd] = sv;
    __syncthreads();
    float sv0 = sumVp[lane]      + sumVp[68 + lane]      + sumVp[136 + lane]      + sumVp[204 + lane];
    float sv1 = sumVp[lane + 32] + sumVp[68 + lane + 32] + sumVp[136 + lane + 32] + sumVp[204 + lane + 32];

    // finalize: denom per row via warp reduction, write to g_A [t][c]
    const int b_ = bh >> 2, h = bh & 3;
    const int tbase = (b_ * 4096 + qt * 64);
    #pragma unroll
    for (int i = 0; i < 8; i++) {
        float ds = dl[i];
        #pragma unroll
        for (int msk = 16; msk >= 1; msk >>= 1)
            ds += __shfl_xor_sync(0xffffffffu, ds, msk);
        float inv = 1.0f / (4096.0f + ds);
        int t = tbase + r0 + i;
        g_A[t * 256 + h * 64 + lane]      = (sv0 + O[i][0]) * inv;
        g_A[t * 256 + h * 64 + lane + 32] = (sv1 + O[i][1]) * inv;
    }
}

// ---------------------------------------------------------------------------
// Output projection: out[t,c] = sum_d g_A[t,d] * o_w[c,d] + o_b[c]
// ---------------------------------------------------------------------------
__global__ __launch_bounds__(256) void oproj_kernel(
    const float* __restrict__ ow, const float* __restrict__ ob,
    float* __restrict__ out)
{
    __shared__ float As[64 * PITCH];
    __shared__ float Ws[64 * PITCH];

    const int tr = blockIdx.x * 64;
    const int tc = blockIdx.y * 64;
    const int tid = threadIdx.x;
    const int tx = tid & 15, ty = tid >> 4;

    float acc[4][4] = {};

    for (int kb_ = 0; kb_ < 256; kb_ += 64) {
        for (int idx = tid; idx < 64 * 64; idx += 256) {
            int r = idx >> 6, d = idx & 63;
            As[r * PITCH + d] = g_A[(tr + r) * 256 + kb_ + d];
            Ws[r * PITCH + d] = ow[(tc + r) * 256 + kb_ + d];
        }
        __syncthreads();
        #pragma unroll 8
        for (int d = 0; d < 64; d++) {
            float a[4], b[4];
            #pragma unroll
            for (int i = 0; i < 4; i++) a[i] = As[(ty * 4 + i) * PITCH + d];
            #pragma unroll
            for (int j = 0; j < 4; j++) b[j] = Ws[(tx + 16 * j) * PITCH + d];
            #pragma unroll
            for (int i = 0; i < 4; i++)
                #pragma unroll
                for (int j = 0; j < 4; j++)
                    acc[i][j] += a[i] * b[j];
        }
        __syncthreads();
    }

    #pragma unroll
    for (int i = 0; i < 4; i++) {
        int t = tr + ty * 4 + i;
        #pragma unroll
        for (int j = 0; j < 4; j++) {
            int c = tc + tx + 16 * j;
            out[t * 256 + c] = acc[i][j] + ob[c];
        }
    }
}

// ---------------------------------------------------------------------------
extern "C" void kernel_launch(void* const* d_in, const int* in_sizes, int n_in,
                              void* d_out, int out_size)
{
    const float* x   = (const float*)d_in[0];
    const float* qw  = (const float*)d_in[1];
    const float* qb  = (const float*)d_in[2];
    const float* kw  = (const float*)d_in[3];
    const float* kb  = (const float*)d_in[4];
    const float* vw  = (const float*)d_in[5];
    const float* vb  = (const float*)d_in[6];
    const float* ow  = (const float*)d_in[7];
    const float* ob  = (const float*)d_in[8];
    const float* tau = (const float*)d_in[9];
    float* out = (float*)d_out;

    // QKV projections
    dim3 gq(128, 4, 3);
    qkv_kernel<<<gq, 256>>>(x, qw, qb, kw, kb, vw, vb);

    // sparse-gated attention
    static bool attr_set = false;
    const int smem_bytes = (64 * QP + 256 * PITCH + 4 * 68) * (int)sizeof(float);
    if (!attr_set) {
        cudaFuncSetAttribute(attn_kernel,
                             cudaFuncAttributeMaxDynamicSharedMemorySize,
                             smem_bytes);
        attr_set = true;
    }
    dim3 ga(64, 8);
    attn_kernel<<<ga, 256, smem_bytes>>>(tau);

    // output projection
    dim3 go(128, 4);
    oproj_kernel<<<go, 256>>>(ow, ob, out);
}